// round 8
// baseline (speedup 1.0000x reference)
#include <cuda_runtime.h>
#include <cuda_fp16.h>
#include <cuda_bf16.h>

#define N_MAX   100000
#define E_TOT_MAX 1700000
#define IN_F    128
#define HID     64
#define NCLS    16
#define CAP1    96
#define CAP2    96

// ---------------- scratch (device globals) ----------------
__device__ __half2 g_h1h[N_MAX * 32];   // x @ W1, fp16 pairs (only agg1 reads it)
__device__ float g_h2 [N_MAX * NCLS];
__device__ float g_es1[N_MAX], g_ed1[N_MAX];
__device__ float g_es2[N_MAX], g_ed2[N_MAX];
__device__ int   g_deg[N_MAX];
__device__ int   g_cur[N_MAX];
__device__ int   g_rowptr[N_MAX + 1];
__device__ int   g_srcs[E_TOT_MAX];
__device__ int   g_part[512];

// ---------------- helpers ----------------
__device__ __forceinline__ float warpMax(float v) {
    #pragma unroll
    for (int o = 16; o; o >>= 1) v = fmaxf(v, __shfl_xor_sync(0xffffffffu, v, o));
    return v;
}
__device__ __forceinline__ float warpSum(float v) {
    #pragma unroll
    for (int o = 16; o; o >>= 1) v += __shfl_xor_sync(0xffffffffu, v, o);
    return v;
}
__device__ __forceinline__ unsigned long long pk2(float v) {
    unsigned long long r;
    asm("mov.b64 %0, {%1, %1};" : "=l"(r) : "f"(v));
    return r;
}
__device__ __forceinline__ unsigned long long fma2(unsigned long long a,
                                                   unsigned long long b,
                                                   unsigned long long c) {
    unsigned long long d;
    asm("fma.rn.f32x2 %0, %1, %2, %3;" : "=l"(d) : "l"(a), "l"(b), "l"(c));
    return d;
}
__device__ __forceinline__ float2 upk(unsigned long long p) {
    float2 f;
    asm("mov.b64 {%0, %1}, %2;" : "=f"(f.x), "=f"(f.y) : "l"(p));
    return f;
}
struct alignas(8) H2x2 { __half2 a, b; };

// ---------------- kernels ----------------
__global__ void k_zero(int n) {
    int i = blockIdx.x * blockDim.x + threadIdx.x;
    if (i < n) g_deg[i] = 1;   // self-loop pre-counted
}

// GEMM1 (fused es1/ed1): h1 = x @ W1 stored fp16.
__global__ void k_gemm1(const float* __restrict__ x, const float* __restrict__ W1,
                        const float* __restrict__ as1, const float* __restrict__ ad1,
                        int n) {
    __shared__ float xs[64][33];
    __shared__ float ws[32][64];
    __shared__ float esr[64][17];
    __shared__ float edr[64][17];
    int t = threadIdx.x;
    int br = blockIdx.x * 64;
    int tr = t >> 4, tc = t & 15;
    int r0 = tr * 4, c0 = tc * 4;
    unsigned long long accp[4][2] = {};
    for (int kc = 0; kc < IN_F; kc += 32) {
        #pragma unroll
        for (int i4 = t; i4 < 512; i4 += 256) {
            int r = i4 >> 3, q = i4 & 7;
            int gr = br + r;
            float4 v = make_float4(0.f, 0.f, 0.f, 0.f);
            if (gr < n) v = *(const float4*)(x + (size_t)gr * IN_F + kc + q * 4);
            xs[r][q * 4 + 0] = v.x; xs[r][q * 4 + 1] = v.y;
            xs[r][q * 4 + 2] = v.z; xs[r][q * 4 + 3] = v.w;
        }
        #pragma unroll
        for (int i4 = t; i4 < 512; i4 += 256)
            ((float4*)ws)[i4] = ((const float4*)(W1 + kc * HID))[i4];
        __syncthreads();
        #pragma unroll 4
        for (int k = 0; k < 32; k++) {
            unsigned long long pa0 = pk2(xs[r0 + 0][k]);
            unsigned long long pa1 = pk2(xs[r0 + 1][k]);
            unsigned long long pa2 = pk2(xs[r0 + 2][k]);
            unsigned long long pa3 = pk2(xs[r0 + 3][k]);
            const unsigned long long* wp = (const unsigned long long*)&ws[k][c0];
            unsigned long long b0 = wp[0], b1 = wp[1];
            accp[0][0] = fma2(pa0, b0, accp[0][0]); accp[0][1] = fma2(pa0, b1, accp[0][1]);
            accp[1][0] = fma2(pa1, b0, accp[1][0]); accp[1][1] = fma2(pa1, b1, accp[1][1]);
            accp[2][0] = fma2(pa2, b0, accp[2][0]); accp[2][1] = fma2(pa2, b1, accp[2][1]);
            accp[3][0] = fma2(pa3, b0, accp[3][0]); accp[3][1] = fma2(pa3, b1, accp[3][1]);
        }
        __syncthreads();
    }
    float as_l[4], ad_l[4];
    #pragma unroll
    for (int j = 0; j < 4; j++) { as_l[j] = as1[c0 + j]; ad_l[j] = ad1[c0 + j]; }
    #pragma unroll
    for (int i = 0; i < 4; i++) {
        float2 p0 = upk(accp[i][0]), p1 = upk(accp[i][1]);
        float a0 = p0.x, a1 = p0.y, a2 = p1.x, a3 = p1.y;
        int gr = br + r0 + i;
        if (gr < n) {
            H2x2 pkh;
            pkh.a = __floats2half2_rn(a0, a1);
            pkh.b = __floats2half2_rn(a2, a3);
            *(H2x2*)(g_h1h + (size_t)gr * 32 + (c0 >> 1)) = pkh;
        }
        esr[r0 + i][tc] = a0 * as_l[0] + a1 * as_l[1] + a2 * as_l[2] + a3 * as_l[3];
        edr[r0 + i][tc] = a0 * ad_l[0] + a1 * ad_l[1] + a2 * ad_l[2] + a3 * ad_l[3];
    }
    __syncthreads();
    if (t < 64) {
        int gr = br + t;
        if (gr < n) {
            float es = 0.f, ed = 0.f;
            #pragma unroll
            for (int c = 0; c < 16; c++) { es += esr[t][c]; ed += edr[t][c]; }
            g_es1[gr] = es; g_ed1[gr] = ed;
        }
    }
}

__global__ void k_hist(const int* __restrict__ ei, int E) {
    int e = blockIdx.x * blockDim.x + threadIdx.x;
    if (e >= E) return;
    atomicAdd(&g_deg[ei[E + e]], 1);
}

__global__ void k_scan_a(int n) {
    __shared__ int s[1024];
    int t = threadIdx.x;
    int i = blockIdx.x * 1024 + t;
    int v = (i < n) ? g_deg[i] : 0;
    s[t] = v;
    #pragma unroll
    for (int off = 1; off < 1024; off <<= 1) {
        __syncthreads();
        int add = (t >= off) ? s[t - off] : 0;
        __syncthreads();
        s[t] += add;
    }
    __syncthreads();
    if (i < n) g_rowptr[i + 1] = s[t];
    if (t == 1023) g_part[blockIdx.x] = s[1023];
}

__global__ void k_scan_b(int nsb) {
    __shared__ int s[512];
    int t = threadIdx.x;
    s[t] = (t < nsb) ? g_part[t] : 0;
    #pragma unroll
    for (int off = 1; off < 512; off <<= 1) {
        __syncthreads();
        int add = (t >= off) ? s[t - off] : 0;
        __syncthreads();
        s[t] += add;
    }
    __syncthreads();
    if (t < nsb) g_part[t] = (t == 0) ? 0 : s[t - 1];  // exclusive
}

// finalize rowptr; place self-loop at rowptr[i], seed cursor past it
__global__ void k_scan_c(int n) {
    int t = threadIdx.x;
    int i = blockIdx.x * 1024 + t;
    if (i < n) {
        int v = g_rowptr[i + 1] + g_part[blockIdx.x];
        g_rowptr[i + 1] = v;
        if (i + 1 < n) { g_srcs[v] = i + 1; g_cur[i + 1] = v + 1; }
    }
    if (i == 0) { g_rowptr[0] = 0; g_srcs[0] = 0; g_cur[0] = 1; }
}

__global__ void k_scatter(const int* __restrict__ ei, int E) {
    int e = blockIdx.x * blockDim.x + threadIdx.x;
    if (e >= E) return;
    int src = ei[e], dst = ei[E + e];
    int pos = atomicAdd(&g_cur[dst], 1);
    g_srcs[pos] = src;
}

// ---------------- agg1 with fused GEMM2 epilogue ----------------
__global__ void k_agg1(const float* __restrict__ b1, const float* __restrict__ W2,
                       const float* __restrict__ as2, const float* __restrict__ ad2,
                       int n) {
    __shared__ float se[8][CAP1];
    __shared__ float2 w2t[16][32];   // w2t[c][l] = (W2[2l][c], W2[2l+1][c])
    __shared__ float s_as[16], s_ad[16];
    int tid = threadIdx.x;
    #pragma unroll
    for (int i = tid; i < 512; i += 256) {
        int c = i >> 5, l = i & 31;
        w2t[c][l] = make_float2(W2[(2 * l) * NCLS + c], W2[(2 * l + 1) * NCLS + c]);
    }
    if (tid < 16) { s_as[tid] = as2[tid]; s_ad[tid] = ad2[tid]; }
    __syncthreads();

    int wslot = tid >> 5;
    int w = (blockIdx.x * blockDim.x + tid) >> 5;
    int lane = tid & 31;
    if (w >= n) return;
    int beg = g_rowptr[w];
    int deg = g_rowptr[w + 1] - beg;
    float ed = g_ed1[w];
    float m = -1e30f;
    for (int j = lane; j < deg; j += 32) {
        int s = g_srcs[beg + j];
        float e = g_es1[s] + ed;
        e = (e >= 0.f) ? e : 0.2f * e;
        if (j < CAP1) se[wslot][j] = e;
        m = fmaxf(m, e);
    }
    m = warpMax(m);
    __syncwarp();
    float z = 0.f, a0 = 0.f, a1 = 0.f;
    int lim = deg < CAP1 ? deg : CAP1;
    #pragma unroll 4
    for (int j = 0; j < lim; j++) {
        float wt = __expf(se[wslot][j] - m);
        int s = g_srcs[beg + j];
        z += wt;
        float2 f = __half22float2(g_h1h[(size_t)s * 32 + lane]);
        a0 += wt * f.x; a1 += wt * f.y;
    }
    for (int j = lim; j < deg; j++) {
        int s = g_srcs[beg + j];
        float e = g_es1[s] + ed;
        e = (e >= 0.f) ? e : 0.2f * e;
        float wt = __expf(e - m);
        z += wt;
        float2 f = __half22float2(g_h1h[(size_t)s * 32 + lane]);
        a0 += wt * f.x; a1 += wt * f.y;
    }
    float inv = 1.f / z;
    float2 bb = ((const float2*)b1)[lane];
    float v0 = a0 * inv + bb.x;
    float v1 = a1 * inv + bb.y;
    v0 = v0 > 0.f ? v0 : 0.f;   // relu(hid)
    v1 = v1 > 0.f ? v1 : 0.f;

    // fused GEMM2: p[c] = this lane's partial of (hid @ W2)[w][c]
    float p[16];
    #pragma unroll
    for (int c = 0; c < 16; c++) {
        float2 wv = w2t[c][lane];
        p[c] = v0 * wv.x + v1 * wv.y;
    }
    // reduce-scatter butterfly (send the half you discard)
    {   int bit = (lane >> 4) & 1;
        #pragma unroll
        for (int j = 0; j < 8; j++) {
            float lo = p[j], hi = p[j + 8];
            float keep = bit ? hi : lo, send = bit ? lo : hi;
            p[j] = keep + __shfl_xor_sync(0xffffffffu, send, 16);
        } }
    {   int bit = (lane >> 3) & 1;
        #pragma unroll
        for (int j = 0; j < 4; j++) {
            float lo = p[j], hi = p[j + 4];
            float keep = bit ? hi : lo, send = bit ? lo : hi;
            p[j] = keep + __shfl_xor_sync(0xffffffffu, send, 8);
        } }
    {   int bit = (lane >> 2) & 1;
        #pragma unroll
        for (int j = 0; j < 2; j++) {
            float lo = p[j], hi = p[j + 2];
            float keep = bit ? hi : lo, send = bit ? lo : hi;
            p[j] = keep + __shfl_xor_sync(0xffffffffu, send, 4);
        } }
    {   int bit = (lane >> 1) & 1;
        float lo = p[0], hi = p[1];
        float keep = bit ? hi : lo, send = bit ? lo : hi;
        p[0] = keep + __shfl_xor_sync(0xffffffffu, send, 2);
    }
    p[0] += __shfl_xor_sync(0xffffffffu, p[0], 1);
    int cls = (((lane >> 4) & 1) << 3) | (((lane >> 3) & 1) << 2) |
              (((lane >> 2) & 1) << 1) | ((lane >> 1) & 1);
    float es = warpSum(p[0] * s_as[cls]) * 0.5f;   // each class on 2 lanes -> x0.5
    float edv = warpSum(p[0] * s_ad[cls]) * 0.5f;
    if ((lane & 1) == 0) g_h2[(size_t)w * NCLS + cls] = p[0];
    if (lane == 0) { g_es2[w] = es; g_ed2[w] = edv; }
}

// ---------------- agg2 + bias + log_softmax: HALF-warp per dst ----------------
__global__ void k_agg2(const float* __restrict__ b2, float* __restrict__ out, int n) {
    __shared__ float se[16][CAP2];
    int hw = threadIdx.x >> 4;
    int node = (blockIdx.x * blockDim.x + threadIdx.x) >> 4;
    int fl = threadIdx.x & 15;
    unsigned gmask = 0xFFFFu << (threadIdx.x & 16);
    if (node >= n) return;
    int beg = g_rowptr[node];
    int deg = g_rowptr[node + 1] - beg;
    float ed = g_ed2[node];
    float m = -1e30f;
    for (int j = fl; j < deg; j += 16) {
        int s = g_srcs[beg + j];
        float e = g_es2[s] + ed;
        e = (e >= 0.f) ? e : 0.2f * e;
        if (j < CAP2) se[hw][j] = e;
        m = fmaxf(m, e);
    }
    #pragma unroll
    for (int o = 8; o; o >>= 1) m = fmaxf(m, __shfl_xor_sync(gmask, m, o, 16));
    __syncwarp(gmask);
    float z = 0.f, acc = 0.f;
    int lim = deg < CAP2 ? deg : CAP2;
    #pragma unroll 4
    for (int j = 0; j < lim; j++) {
        float wt = __expf(se[hw][j] - m);
        int s = g_srcs[beg + j];
        z += wt;
        acc += wt * g_h2[(size_t)s * NCLS + fl];
    }
    for (int j = lim; j < deg; j++) {
        int s = g_srcs[beg + j];
        float e = g_es2[s] + ed;
        e = (e >= 0.f) ? e : 0.2f * e;
        float wt = __expf(e - m);
        z += wt;
        acc += wt * g_h2[(size_t)s * NCLS + fl];
    }
    float val = acc / z + b2[fl];
    float mx = val;
    #pragma unroll
    for (int o = 8; o; o >>= 1) mx = fmaxf(mx, __shfl_xor_sync(gmask, mx, o, 16));
    float ex = __expf(val - mx);
    float sev = ex;
    #pragma unroll
    for (int o = 8; o; o >>= 1) sev += __shfl_xor_sync(gmask, sev, o, 16);
    out[(size_t)node * NCLS + fl] = val - mx - logf(sev);
}

// ---------------- launch (single stream, graph-capture safe) ----------------
extern "C" void kernel_launch(void* const* d_in, const int* in_sizes, int n_in,
                              void* d_out, int out_size) {
    const float* x   = (const float*)d_in[0];
    const int*   ei  = (const int*)d_in[1];
    const float* W1  = (const float*)d_in[2];
    const float* as1 = (const float*)d_in[3];
    const float* ad1 = (const float*)d_in[4];
    const float* b1  = (const float*)d_in[5];
    const float* W2  = (const float*)d_in[6];
    const float* as2 = (const float*)d_in[7];
    const float* ad2 = (const float*)d_in[8];
    const float* b2  = (const float*)d_in[9];
    float* out = (float*)d_out;

    int N  = in_sizes[0] / IN_F;
    int E  = in_sizes[1] / 2;
    int nsb = (N + 1023) / 1024;

    k_zero   <<<(N + 255) / 256, 256>>>(N);
    k_gemm1  <<<(N + 63) / 64, 256>>>(x, W1, as1, ad1, N);
    k_hist   <<<(E + 255) / 256, 256>>>(ei, E);
    k_scan_a <<<nsb, 1024>>>(N);
    k_scan_b <<<1, 512>>>(nsb);
    k_scan_c <<<nsb, 1024>>>(N);
    k_scatter<<<(E + 255) / 256, 256>>>(ei, E);
    k_agg1   <<<(N + 7) / 8, 256>>>(b1, W2, as2, ad2, N);
    k_agg2   <<<(N + 15) / 16, 256>>>(b2, out, N);
}

// round 10
// speedup vs baseline: 1.2433x; 1.2433x over previous
#include <cuda_runtime.h>
#include <cuda_fp16.h>
#include <cuda_bf16.h>

#define N_MAX   100000
#define E_TOT_MAX 1700000
#define IN_F    128
#define HID     64
#define NCLS    16
#define CAP1    96
#define CAP2    96

// ---------------- scratch (device globals) ----------------
__device__ __half2 g_h1h[N_MAX * 32];   // x @ W1, fp16 pairs (only agg1 reads it)
__device__ float g_hid[N_MAX * HID];
__device__ float g_h2 [N_MAX * NCLS];
__device__ float g_es1[N_MAX], g_ed1[N_MAX];
__device__ float g_es2[N_MAX], g_ed2[N_MAX];
__device__ int   g_deg[N_MAX];
__device__ int   g_cur[N_MAX];
__device__ int   g_rowptr[N_MAX + 1];
__device__ int   g_srcs[E_TOT_MAX];
__device__ int   g_part[512];

// ---------------- helpers ----------------
__device__ __forceinline__ float warpMax(float v) {
    #pragma unroll
    for (int o = 16; o; o >>= 1) v = fmaxf(v, __shfl_xor_sync(0xffffffffu, v, o));
    return v;
}
__device__ __forceinline__ unsigned long long pk2(float v) {
    unsigned long long r;
    asm("mov.b64 %0, {%1, %1};" : "=l"(r) : "f"(v));
    return r;
}
__device__ __forceinline__ unsigned long long fma2(unsigned long long a,
                                                   unsigned long long b,
                                                   unsigned long long c) {
    unsigned long long d;
    asm("fma.rn.f32x2 %0, %1, %2, %3;" : "=l"(d) : "l"(a), "l"(b), "l"(c));
    return d;
}
__device__ __forceinline__ float2 upk(unsigned long long p) {
    float2 f;
    asm("mov.b64 {%0, %1}, %2;" : "=f"(f.x), "=f"(f.y) : "l"(p));
    return f;
}
struct alignas(8) H2x2 { __half2 a, b; };

// ---------------- kernels ----------------
// GEMM1 (fused es1/ed1 + deg init): h1 = x @ W1 stored fp16.
__global__ void k_gemm1(const float* __restrict__ x, const float* __restrict__ W1,
                        const float* __restrict__ as1, const float* __restrict__ ad1,
                        int n) {
    // fold k_zero: grid covers >= n threads; independent of the gemm below
    int gi = blockIdx.x * blockDim.x + threadIdx.x;
    if (gi < n) g_deg[gi] = 1;   // self-loop pre-counted

    __shared__ float xs[64][33];
    __shared__ float ws[32][64];
    __shared__ float esr[64][17];
    __shared__ float edr[64][17];
    int t = threadIdx.x;
    int br = blockIdx.x * 64;
    int tr = t >> 4, tc = t & 15;
    int r0 = tr * 4, c0 = tc * 4;
    unsigned long long accp[4][2] = {};
    for (int kc = 0; kc < IN_F; kc += 32) {
        #pragma unroll
        for (int i4 = t; i4 < 512; i4 += 256) {
            int r = i4 >> 3, q = i4 & 7;
            int gr = br + r;
            float4 v = make_float4(0.f, 0.f, 0.f, 0.f);
            if (gr < n) v = *(const float4*)(x + (size_t)gr * IN_F + kc + q * 4);
            xs[r][q * 4 + 0] = v.x; xs[r][q * 4 + 1] = v.y;
            xs[r][q * 4 + 2] = v.z; xs[r][q * 4 + 3] = v.w;
        }
        #pragma unroll
        for (int i4 = t; i4 < 512; i4 += 256)
            ((float4*)ws)[i4] = ((const float4*)(W1 + kc * HID))[i4];
        __syncthreads();
        #pragma unroll 4
        for (int k = 0; k < 32; k++) {
            unsigned long long pa0 = pk2(xs[r0 + 0][k]);
            unsigned long long pa1 = pk2(xs[r0 + 1][k]);
            unsigned long long pa2 = pk2(xs[r0 + 2][k]);
            unsigned long long pa3 = pk2(xs[r0 + 3][k]);
            const unsigned long long* wp = (const unsigned long long*)&ws[k][c0];
            unsigned long long b0 = wp[0], b1 = wp[1];
            accp[0][0] = fma2(pa0, b0, accp[0][0]); accp[0][1] = fma2(pa0, b1, accp[0][1]);
            accp[1][0] = fma2(pa1, b0, accp[1][0]); accp[1][1] = fma2(pa1, b1, accp[1][1]);
            accp[2][0] = fma2(pa2, b0, accp[2][0]); accp[2][1] = fma2(pa2, b1, accp[2][1]);
            accp[3][0] = fma2(pa3, b0, accp[3][0]); accp[3][1] = fma2(pa3, b1, accp[3][1]);
        }
        __syncthreads();
    }
    float as_l[4], ad_l[4];
    #pragma unroll
    for (int j = 0; j < 4; j++) { as_l[j] = as1[c0 + j]; ad_l[j] = ad1[c0 + j]; }
    #pragma unroll
    for (int i = 0; i < 4; i++) {
        float2 p0 = upk(accp[i][0]), p1 = upk(accp[i][1]);
        float a0 = p0.x, a1 = p0.y, a2 = p1.x, a3 = p1.y;
        int gr = br + r0 + i;
        if (gr < n) {
            H2x2 pkh;
            pkh.a = __floats2half2_rn(a0, a1);
            pkh.b = __floats2half2_rn(a2, a3);
            *(H2x2*)(g_h1h + (size_t)gr * 32 + (c0 >> 1)) = pkh;
        }
        esr[r0 + i][tc] = a0 * as_l[0] + a1 * as_l[1] + a2 * as_l[2] + a3 * as_l[3];
        edr[r0 + i][tc] = a0 * ad_l[0] + a1 * ad_l[1] + a2 * ad_l[2] + a3 * ad_l[3];
    }
    __syncthreads();
    if (t < 64) {
        int gr = br + t;
        if (gr < n) {
            float es = 0.f, ed = 0.f;
            #pragma unroll
            for (int c = 0; c < 16; c++) { es += esr[t][c]; ed += edr[t][c]; }
            g_es1[gr] = es; g_ed1[gr] = ed;
        }
    }
}

__global__ void k_hist(const int* __restrict__ ei, int E) {
    int e = blockIdx.x * blockDim.x + threadIdx.x;
    if (e >= E) return;
    atomicAdd(&g_deg[ei[E + e]], 1);
}

__global__ void k_scan_a(int n) {
    __shared__ int s[1024];
    int t = threadIdx.x;
    int i = blockIdx.x * 1024 + t;
    int v = (i < n) ? g_deg[i] : 0;
    s[t] = v;
    #pragma unroll
    for (int off = 1; off < 1024; off <<= 1) {
        __syncthreads();
        int add = (t >= off) ? s[t - off] : 0;
        __syncthreads();
        s[t] += add;
    }
    __syncthreads();
    if (i < n) g_rowptr[i + 1] = s[t];
    if (t == 1023) g_part[blockIdx.x] = s[1023];
}

__global__ void k_scan_b(int nsb) {
    __shared__ int s[512];
    int t = threadIdx.x;
    s[t] = (t < nsb) ? g_part[t] : 0;
    #pragma unroll
    for (int off = 1; off < 512; off <<= 1) {
        __syncthreads();
        int add = (t >= off) ? s[t - off] : 0;
        __syncthreads();
        s[t] += add;
    }
    __syncthreads();
    if (t < nsb) g_part[t] = (t == 0) ? 0 : s[t - 1];  // exclusive
}

// finalize rowptr; place self-loop at rowptr[i], seed cursor past it
__global__ void k_scan_c(int n) {
    int t = threadIdx.x;
    int i = blockIdx.x * 1024 + t;
    if (i < n) {
        int v = g_rowptr[i + 1] + g_part[blockIdx.x];
        g_rowptr[i + 1] = v;
        if (i + 1 < n) { g_srcs[v] = i + 1; g_cur[i + 1] = v + 1; }
    }
    if (i == 0) { g_rowptr[0] = 0; g_srcs[0] = 0; g_cur[0] = 1; }
}

__global__ void k_scatter(const int* __restrict__ ei, int E) {
    int e = blockIdx.x * blockDim.x + threadIdx.x;
    if (e >= E) return;
    int src = ei[e], dst = ei[E + e];
    int pos = atomicAdd(&g_cur[dst], 1);
    g_srcs[pos] = src;
}

// agg1: warp per dst, 2 edges/iter (half-warp each, uint2 loads), smem logit+src cache
__global__ void k_agg1(const float* __restrict__ b1, int n) {
    __shared__ float se[8][CAP1];
    __shared__ int   ss[8][CAP1];
    int wslot = threadIdx.x >> 5;
    int w = (blockIdx.x * blockDim.x + threadIdx.x) >> 5;
    int lane = threadIdx.x & 31;
    if (w >= n) return;
    int beg = g_rowptr[w];
    int deg = g_rowptr[w + 1] - beg;
    float ed = g_ed1[w];
    float m = -1e30f;
    for (int j = lane; j < deg; j += 32) {
        int s = g_srcs[beg + j];
        float e = g_es1[s] + ed;
        e = (e >= 0.f) ? e : 0.2f * e;
        if (j < CAP1) { se[wslot][j] = e; ss[wslot][j] = s; }
        m = fmaxf(m, e);
    }
    m = warpMax(m);
    __syncwarp();
    int half = lane >> 4, fl = lane & 15;
    float z = 0.f, a0 = 0.f, a1 = 0.f, a2 = 0.f, a3 = 0.f;
    #pragma unroll 2
    for (int j = half; j < deg; j += 2) {
        int s; float e;
        if (j < CAP1) { s = ss[wslot][j]; e = se[wslot][j]; }
        else {
            s = g_srcs[beg + j];
            e = g_es1[s] + ed;
            e = (e >= 0.f) ? e : 0.2f * e;
        }
        float wt = __expf(e - m);
        z += wt;
        uint2 hv = ((const uint2*)(g_h1h + (size_t)s * 32))[fl];
        float2 f0 = __half22float2(*(__half2*)&hv.x);
        float2 f1 = __half22float2(*(__half2*)&hv.y);
        a0 += wt * f0.x; a1 += wt * f0.y; a2 += wt * f1.x; a3 += wt * f1.y;
    }
    // combine the two halves
    z  += __shfl_xor_sync(0xffffffffu, z, 16);
    a0 += __shfl_xor_sync(0xffffffffu, a0, 16);
    a1 += __shfl_xor_sync(0xffffffffu, a1, 16);
    a2 += __shfl_xor_sync(0xffffffffu, a2, 16);
    a3 += __shfl_xor_sync(0xffffffffu, a3, 16);
    if (half == 0) {
        float inv = 1.f / z;
        float4 bb = ((const float4*)b1)[fl];
        float v0 = a0 * inv + bb.x;
        float v1 = a1 * inv + bb.y;
        float v2 = a2 * inv + bb.z;
        float v3 = a3 * inv + bb.w;
        float4 o;
        o.x = v0 > 0.f ? v0 : 0.f;
        o.y = v1 > 0.f ? v1 : 0.f;
        o.z = v2 > 0.f ? v2 : 0.f;
        o.w = v3 > 0.f ? v3 : 0.f;
        ((float4*)(g_hid + (size_t)w * HID))[fl] = o;
    }
}

// GEMM2 (fused es2/ed2): thread per node, packed f32x2
__global__ void k_gemm2(const float* __restrict__ W2, const float* __restrict__ as2,
                        const float* __restrict__ ad2, int n) {
    __shared__ float ws2[64][16];
    __shared__ float s_as[16], s_ad[16];
    int t = threadIdx.x;
    if (t < 256) ((float4*)ws2)[t] = ((const float4*)W2)[t];
    if (t < 16) { s_as[t] = as2[t]; s_ad[t] = ad2[t]; }
    __syncthreads();
    int nidx = blockIdx.x * blockDim.x + t;
    if (nidx >= n) return;
    unsigned long long accp[8] = {};
    const float4* row = (const float4*)(g_hid + (size_t)nidx * HID);
    #pragma unroll
    for (int k4 = 0; k4 < 16; k4++) {
        float4 h = row[k4];
        float hv[4] = {h.x, h.y, h.z, h.w};
        #pragma unroll
        for (int kk = 0; kk < 4; kk++) {
            int k = k4 * 4 + kk;
            unsigned long long pv = pk2(hv[kk]);
            const unsigned long long* wp = (const unsigned long long*)&ws2[k][0];
            #pragma unroll
            for (int p = 0; p < 8; p++) accp[p] = fma2(pv, wp[p], accp[p]);
        }
    }
    float a[16];
    #pragma unroll
    for (int p = 0; p < 8; p++) { float2 u = upk(accp[p]); a[2 * p] = u.x; a[2 * p + 1] = u.y; }
    float es = 0.f, ed = 0.f;
    #pragma unroll
    for (int j = 0; j < 16; j++) { es += a[j] * s_as[j]; ed += a[j] * s_ad[j]; }
    float4* outp = (float4*)(g_h2 + (size_t)nidx * NCLS);
    outp[0] = make_float4(a[0],  a[1],  a[2],  a[3]);
    outp[1] = make_float4(a[4],  a[5],  a[6],  a[7]);
    outp[2] = make_float4(a[8],  a[9],  a[10], a[11]);
    outp[3] = make_float4(a[12], a[13], a[14], a[15]);
    g_es2[nidx] = es; g_ed2[nidx] = ed;
}

// agg2 + bias + log_softmax: HALF-warp per dst, smem logit+src cache
__global__ void k_agg2(const float* __restrict__ b2, float* __restrict__ out, int n) {
    __shared__ float se[16][CAP2];
    __shared__ int   ss[16][CAP2];
    int hw = threadIdx.x >> 4;
    int node = (blockIdx.x * blockDim.x + threadIdx.x) >> 4;
    int fl = threadIdx.x & 15;
    unsigned gmask = 0xFFFFu << (threadIdx.x & 16);
    if (node >= n) return;
    int beg = g_rowptr[node];
    int deg = g_rowptr[node + 1] - beg;
    float ed = g_ed2[node];
    float m = -1e30f;
    for (int j = fl; j < deg; j += 16) {
        int s = g_srcs[beg + j];
        float e = g_es2[s] + ed;
        e = (e >= 0.f) ? e : 0.2f * e;
        if (j < CAP2) { se[hw][j] = e; ss[hw][j] = s; }
        m = fmaxf(m, e);
    }
    #pragma unroll
    for (int o = 8; o; o >>= 1) m = fmaxf(m, __shfl_xor_sync(gmask, m, o, 16));
    __syncwarp(gmask);
    float z = 0.f, acc = 0.f;
    int lim = deg < CAP2 ? deg : CAP2;
    #pragma unroll 4
    for (int j = 0; j < lim; j++) {
        float wt = __expf(se[hw][j] - m);
        int s = ss[hw][j];
        z += wt;
        acc += wt * g_h2[(size_t)s * NCLS + fl];
    }
    for (int j = lim; j < deg; j++) {
        int s = g_srcs[beg + j];
        float e = g_es2[s] + ed;
        e = (e >= 0.f) ? e : 0.2f * e;
        float wt = __expf(e - m);
        z += wt;
        acc += wt * g_h2[(size_t)s * NCLS + fl];
    }
    float val = acc / z + b2[fl];
    float mx = val;
    #pragma unroll
    for (int o = 8; o; o >>= 1) mx = fmaxf(mx, __shfl_xor_sync(gmask, mx, o, 16));
    float ex = __expf(val - mx);
    float sev = ex;
    #pragma unroll
    for (int o = 8; o; o >>= 1) sev += __shfl_xor_sync(gmask, sev, o, 16);
    out[(size_t)node * NCLS + fl] = val - mx - logf(sev);
}

// ---------------- launch (single stream, graph-capture safe) ----------------
extern "C" void kernel_launch(void* const* d_in, const int* in_sizes, int n_in,
                              void* d_out, int out_size) {
    const float* x   = (const float*)d_in[0];
    const int*   ei  = (const int*)d_in[1];
    const float* W1  = (const float*)d_in[2];
    const float* as1 = (const float*)d_in[3];
    const float* ad1 = (const float*)d_in[4];
    const float* b1  = (const float*)d_in[5];
    const float* W2  = (const float*)d_in[6];
    const float* as2 = (const float*)d_in[7];
    const float* ad2 = (const float*)d_in[8];
    const float* b2  = (const float*)d_in[9];
    float* out = (float*)d_out;

    int N  = in_sizes[0] / IN_F;
    int E  = in_sizes[1] / 2;
    int nsb = (N + 1023) / 1024;

    k_gemm1  <<<(N + 63) / 64, 256>>>(x, W1, as1, ad1, N);
    k_hist   <<<(E + 255) / 256, 256>>>(ei, E);
    k_scan_a <<<nsb, 1024>>>(N);
    k_scan_b <<<1, 512>>>(nsb);
    k_scan_c <<<nsb, 1024>>>(N);
    k_scatter<<<(E + 255) / 256, 256>>>(ei, E);
    k_agg1   <<<(N + 7) / 8, 256>>>(b1, N);
    k_gemm2  <<<(N + 255) / 256, 256>>>(W2, as2, ad2, N);
    k_agg2   <<<(N + 15) / 16, 256>>>(b2, out, N);
}

// round 11
// speedup vs baseline: 1.2710x; 1.0223x over previous
#include <cuda_runtime.h>
#include <cuda_fp16.h>
#include <cuda_bf16.h>

#define N_MAX   100000
#define E_TOT_MAX 1700000
#define IN_F    128
#define HID     64
#define NCLS    16
#define CAP1    96
#define CAP2    96

// ---------------- scratch (device globals) ----------------
__device__ __half2 g_h1h[N_MAX * 32];   // x @ W1, fp16 pairs (only agg1 reads it)
__device__ float g_hid[N_MAX * HID];
__device__ float g_h2 [N_MAX * NCLS];
__device__ float g_es1[N_MAX], g_ed1[N_MAX];
__device__ float g_es2[N_MAX], g_ed2[N_MAX];
__device__ int   g_deg[N_MAX];
__device__ int   g_cur[N_MAX];
__device__ int   g_rowptr[N_MAX + 1];
__device__ int   g_srcs[E_TOT_MAX];
__device__ int   g_part[512];

// ---------------- helpers ----------------
__device__ __forceinline__ float warpMax(float v) {
    #pragma unroll
    for (int o = 16; o; o >>= 1) v = fmaxf(v, __shfl_xor_sync(0xffffffffu, v, o));
    return v;
}
__device__ __forceinline__ int warpSumI(int v) {
    #pragma unroll
    for (int o = 16; o; o >>= 1) v += __shfl_xor_sync(0xffffffffu, v, o);
    return v;
}
__device__ __forceinline__ unsigned long long pk2(float v) {
    unsigned long long r;
    asm("mov.b64 %0, {%1, %1};" : "=l"(r) : "f"(v));
    return r;
}
__device__ __forceinline__ unsigned long long fma2(unsigned long long a,
                                                   unsigned long long b,
                                                   unsigned long long c) {
    unsigned long long d;
    asm("fma.rn.f32x2 %0, %1, %2, %3;" : "=l"(d) : "l"(a), "l"(b), "l"(c));
    return d;
}
__device__ __forceinline__ float2 upk(unsigned long long p) {
    float2 f;
    asm("mov.b64 {%0, %1}, %2;" : "=f"(f.x), "=f"(f.y) : "l"(p));
    return f;
}
struct alignas(8) H2x2 { __half2 a, b; };

// ---------------- kernels ----------------
// GEMM1 (fused es1/ed1 + deg init): h1 = x @ W1 stored fp16.
__global__ void k_gemm1(const float* __restrict__ x, const float* __restrict__ W1,
                        const float* __restrict__ as1, const float* __restrict__ ad1,
                        int n) {
    int gi = blockIdx.x * blockDim.x + threadIdx.x;
    if (gi < n) g_deg[gi] = 1;   // self-loop pre-counted

    __shared__ float xs[64][33];
    __shared__ float ws[32][64];
    __shared__ float esr[64][17];
    __shared__ float edr[64][17];
    int t = threadIdx.x;
    int br = blockIdx.x * 64;
    int tr = t >> 4, tc = t & 15;
    int r0 = tr * 4, c0 = tc * 4;
    unsigned long long accp[4][2] = {};
    for (int kc = 0; kc < IN_F; kc += 32) {
        #pragma unroll
        for (int i4 = t; i4 < 512; i4 += 256) {
            int r = i4 >> 3, q = i4 & 7;
            int gr = br + r;
            float4 v = make_float4(0.f, 0.f, 0.f, 0.f);
            if (gr < n) v = *(const float4*)(x + (size_t)gr * IN_F + kc + q * 4);
            xs[r][q * 4 + 0] = v.x; xs[r][q * 4 + 1] = v.y;
            xs[r][q * 4 + 2] = v.z; xs[r][q * 4 + 3] = v.w;
        }
        #pragma unroll
        for (int i4 = t; i4 < 512; i4 += 256)
            ((float4*)ws)[i4] = ((const float4*)(W1 + kc * HID))[i4];
        __syncthreads();
        #pragma unroll 4
        for (int k = 0; k < 32; k++) {
            unsigned long long pa0 = pk2(xs[r0 + 0][k]);
            unsigned long long pa1 = pk2(xs[r0 + 1][k]);
            unsigned long long pa2 = pk2(xs[r0 + 2][k]);
            unsigned long long pa3 = pk2(xs[r0 + 3][k]);
            const unsigned long long* wp = (const unsigned long long*)&ws[k][c0];
            unsigned long long b0 = wp[0], b1 = wp[1];
            accp[0][0] = fma2(pa0, b0, accp[0][0]); accp[0][1] = fma2(pa0, b1, accp[0][1]);
            accp[1][0] = fma2(pa1, b0, accp[1][0]); accp[1][1] = fma2(pa1, b1, accp[1][1]);
            accp[2][0] = fma2(pa2, b0, accp[2][0]); accp[2][1] = fma2(pa2, b1, accp[2][1]);
            accp[3][0] = fma2(pa3, b0, accp[3][0]); accp[3][1] = fma2(pa3, b1, accp[3][1]);
        }
        __syncthreads();
    }
    float as_l[4], ad_l[4];
    #pragma unroll
    for (int j = 0; j < 4; j++) { as_l[j] = as1[c0 + j]; ad_l[j] = ad1[c0 + j]; }
    #pragma unroll
    for (int i = 0; i < 4; i++) {
        float2 p0 = upk(accp[i][0]), p1 = upk(accp[i][1]);
        float a0 = p0.x, a1 = p0.y, a2 = p1.x, a3 = p1.y;
        int gr = br + r0 + i;
        if (gr < n) {
            H2x2 pkh;
            pkh.a = __floats2half2_rn(a0, a1);
            pkh.b = __floats2half2_rn(a2, a3);
            *(H2x2*)(g_h1h + (size_t)gr * 32 + (c0 >> 1)) = pkh;
        }
        esr[r0 + i][tc] = a0 * as_l[0] + a1 * as_l[1] + a2 * as_l[2] + a3 * as_l[3];
        edr[r0 + i][tc] = a0 * ad_l[0] + a1 * ad_l[1] + a2 * ad_l[2] + a3 * ad_l[3];
    }
    __syncthreads();
    if (t < 64) {
        int gr = br + t;
        if (gr < n) {
            float es = 0.f, ed = 0.f;
            #pragma unroll
            for (int c = 0; c < 16; c++) { es += esr[t][c]; ed += edr[t][c]; }
            g_es1[gr] = es; g_ed1[gr] = ed;
        }
    }
}

// histogram over dst, 2 edges/thread via int2 (E even)
__global__ void k_hist(const int* __restrict__ ei, int E) {
    int idx = blockIdx.x * blockDim.x + threadIdx.x;
    int Eh = E >> 1;
    if (idx < Eh) {
        int2 dv = ((const int2*)(ei + E))[idx];
        atomicAdd(&g_deg[dv.x], 1);
        atomicAdd(&g_deg[dv.y], 1);
    }
    if ((E & 1) && idx == Eh) atomicAdd(&g_deg[ei[E + E - 1]], 1);
}

__global__ void k_scan_a(int n) {
    __shared__ int s[1024];
    int t = threadIdx.x;
    int i = blockIdx.x * 1024 + t;
    int v = (i < n) ? g_deg[i] : 0;
    s[t] = v;
    #pragma unroll
    for (int off = 1; off < 1024; off <<= 1) {
        __syncthreads();
        int add = (t >= off) ? s[t - off] : 0;
        __syncthreads();
        s[t] += add;
    }
    __syncthreads();
    if (i < n) g_rowptr[i + 1] = s[t];
    if (t == 1023) g_part[blockIdx.x] = s[1023];
}

// finalize rowptr (block computes its own g_part prefix); place self-loop; seed cursor
__global__ void k_scan_c(int n) {
    __shared__ int warpsums[32];
    __shared__ int s_off;
    int t = threadIdx.x;
    int blk = blockIdx.x;
    // block-wide exclusive prefix of g_part: sum of g_part[0..blk-1]
    int v = (t < blk) ? g_part[t] : 0;     // blk <= 97 < 1024 threads
    int wsum = warpSumI(v);
    if ((t & 31) == 0) warpsums[t >> 5] = wsum;
    __syncthreads();
    if (t < 32) {
        int x = (t < (blockDim.x >> 5)) ? warpsums[t] : 0;
        x = warpSumI(x);
        if (t == 0) s_off = x;
    }
    __syncthreads();
    int off = s_off;
    int i = blk * 1024 + t;
    if (i < n) {
        int vv = g_rowptr[i + 1] + off;
        g_rowptr[i + 1] = vv;
        if (i + 1 < n) { g_srcs[vv] = i + 1; g_cur[i + 1] = vv + 1; }
    }
    if (i == 0) { g_rowptr[0] = 0; g_srcs[0] = 0; g_cur[0] = 1; }
}

// scatter, 2 edges/thread via int2 (E even)
__global__ void k_scatter(const int* __restrict__ ei, int E) {
    int idx = blockIdx.x * blockDim.x + threadIdx.x;
    int Eh = E >> 1;
    if (idx < Eh) {
        int2 sv = ((const int2*)ei)[idx];
        int2 dv = ((const int2*)(ei + E))[idx];
        int p0 = atomicAdd(&g_cur[dv.x], 1);
        g_srcs[p0] = sv.x;
        int p1 = atomicAdd(&g_cur[dv.y], 1);
        g_srcs[p1] = sv.y;
    }
    if ((E & 1) && idx == Eh) {
        int src = ei[E - 1], dst = ei[E + E - 1];
        int pos = atomicAdd(&g_cur[dst], 1);
        g_srcs[pos] = src;
    }
}

// agg1: warp per dst, QUARTER-warp per edge (4 edges/iter, uint4 = full 64-feat row)
__global__ void k_agg1(const float* __restrict__ b1, int n) {
    __shared__ float se[8][CAP1];
    __shared__ int   ss[8][CAP1];
    int wslot = threadIdx.x >> 5;
    int w = (blockIdx.x * blockDim.x + threadIdx.x) >> 5;
    int lane = threadIdx.x & 31;
    if (w >= n) return;
    int beg = g_rowptr[w];
    int deg = g_rowptr[w + 1] - beg;
    float ed = g_ed1[w];
    float m = -1e30f;
    for (int j = lane; j < deg; j += 32) {
        int s = g_srcs[beg + j];
        float e = g_es1[s] + ed;
        e = (e >= 0.f) ? e : 0.2f * e;
        if (j < CAP1) { se[wslot][j] = e; ss[wslot][j] = s; }
        m = fmaxf(m, e);
    }
    m = warpMax(m);
    __syncwarp();
    int q = lane >> 3, fl8 = lane & 7;
    float z = 0.f;
    float acc[8] = {};
    for (int j = q; j < deg; j += 4) {
        int s; float e;
        if (j < CAP1) { s = ss[wslot][j]; e = se[wslot][j]; }
        else {
            s = g_srcs[beg + j];
            e = g_es1[s] + ed;
            e = (e >= 0.f) ? e : 0.2f * e;
        }
        float wt = __expf(e - m);
        z += wt;
        uint4 hv = ((const uint4*)(g_h1h + (size_t)s * 32))[fl8];
        float2 f0 = __half22float2(*(__half2*)&hv.x);
        float2 f1 = __half22float2(*(__half2*)&hv.y);
        float2 f2 = __half22float2(*(__half2*)&hv.z);
        float2 f3 = __half22float2(*(__half2*)&hv.w);
        acc[0] += wt * f0.x; acc[1] += wt * f0.y;
        acc[2] += wt * f1.x; acc[3] += wt * f1.y;
        acc[4] += wt * f2.x; acc[5] += wt * f2.y;
        acc[6] += wt * f3.x; acc[7] += wt * f3.y;
    }
    // combine the four quarters (independent shfls, pipelined)
    z += __shfl_xor_sync(0xffffffffu, z, 8);
    z += __shfl_xor_sync(0xffffffffu, z, 16);
    #pragma unroll
    for (int i = 0; i < 8; i++) acc[i] += __shfl_xor_sync(0xffffffffu, acc[i], 8);
    #pragma unroll
    for (int i = 0; i < 8; i++) acc[i] += __shfl_xor_sync(0xffffffffu, acc[i], 16);
    if (q == 0) {
        float inv = 1.f / z;
        const float4* b4 = (const float4*)b1;
        float4 ba = b4[2 * fl8], bbv = b4[2 * fl8 + 1];
        float4 o0, o1;
        o0.x = fmaxf(acc[0] * inv + ba.x, 0.f);
        o0.y = fmaxf(acc[1] * inv + ba.y, 0.f);
        o0.z = fmaxf(acc[2] * inv + ba.z, 0.f);
        o0.w = fmaxf(acc[3] * inv + ba.w, 0.f);
        o1.x = fmaxf(acc[4] * inv + bbv.x, 0.f);
        o1.y = fmaxf(acc[5] * inv + bbv.y, 0.f);
        o1.z = fmaxf(acc[6] * inv + bbv.z, 0.f);
        o1.w = fmaxf(acc[7] * inv + bbv.w, 0.f);
        float4* hp = (float4*)(g_hid + (size_t)w * HID);
        hp[2 * fl8] = o0;
        hp[2 * fl8 + 1] = o1;
    }
}

// GEMM2 (fused es2/ed2): thread per node, packed f32x2
__global__ void k_gemm2(const float* __restrict__ W2, const float* __restrict__ as2,
                        const float* __restrict__ ad2, int n) {
    __shared__ float ws2[64][16];
    __shared__ float s_as[16], s_ad[16];
    int t = threadIdx.x;
    if (t < 256) ((float4*)ws2)[t] = ((const float4*)W2)[t];
    if (t < 16) { s_as[t] = as2[t]; s_ad[t] = ad2[t]; }
    __syncthreads();
    int nidx = blockIdx.x * blockDim.x + t;
    if (nidx >= n) return;
    unsigned long long accp[8] = {};
    const float4* row = (const float4*)(g_hid + (size_t)nidx * HID);
    #pragma unroll
    for (int k4 = 0; k4 < 16; k4++) {
        float4 h = row[k4];
        float hv[4] = {h.x, h.y, h.z, h.w};
        #pragma unroll
        for (int kk = 0; kk < 4; kk++) {
            int k = k4 * 4 + kk;
            unsigned long long pv = pk2(hv[kk]);
            const unsigned long long* wp = (const unsigned long long*)&ws2[k][0];
            #pragma unroll
            for (int p = 0; p < 8; p++) accp[p] = fma2(pv, wp[p], accp[p]);
        }
    }
    float a[16];
    #pragma unroll
    for (int p = 0; p < 8; p++) { float2 u = upk(accp[p]); a[2 * p] = u.x; a[2 * p + 1] = u.y; }
    float es = 0.f, ed = 0.f;
    #pragma unroll
    for (int j = 0; j < 16; j++) { es += a[j] * s_as[j]; ed += a[j] * s_ad[j]; }
    float4* outp = (float4*)(g_h2 + (size_t)nidx * NCLS);
    outp[0] = make_float4(a[0],  a[1],  a[2],  a[3]);
    outp[1] = make_float4(a[4],  a[5],  a[6],  a[7]);
    outp[2] = make_float4(a[8],  a[9],  a[10], a[11]);
    outp[3] = make_float4(a[12], a[13], a[14], a[15]);
    g_es2[nidx] = es; g_ed2[nidx] = ed;
}

// agg2 + bias + log_softmax: HALF-warp per dst, smem logit+src cache
__global__ void k_agg2(const float* __restrict__ b2, float* __restrict__ out, int n) {
    __shared__ float se[16][CAP2];
    __shared__ int   ss[16][CAP2];
    int hw = threadIdx.x >> 4;
    int node = (blockIdx.x * blockDim.x + threadIdx.x) >> 4;
    int fl = threadIdx.x & 15;
    unsigned gmask = 0xFFFFu << (threadIdx.x & 16);
    if (node >= n) return;
    int beg = g_rowptr[node];
    int deg = g_rowptr[node + 1] - beg;
    float ed = g_ed2[node];
    float m = -1e30f;
    for (int j = fl; j < deg; j += 16) {
        int s = g_srcs[beg + j];
        float e = g_es2[s] + ed;
        e = (e >= 0.f) ? e : 0.2f * e;
        if (j < CAP2) { se[hw][j] = e; ss[hw][j] = s; }
        m = fmaxf(m, e);
    }
    #pragma unroll
    for (int o = 8; o; o >>= 1) m = fmaxf(m, __shfl_xor_sync(gmask, m, o, 16));
    __syncwarp(gmask);
    float z = 0.f, acc = 0.f;
    int lim = deg < CAP2 ? deg : CAP2;
    #pragma unroll 4
    for (int j = 0; j < lim; j++) {
        float wt = __expf(se[hw][j] - m);
        int s = ss[hw][j];
        z += wt;
        acc += wt * g_h2[(size_t)s * NCLS + fl];
    }
    for (int j = lim; j < deg; j++) {
        int s = g_srcs[beg + j];
        float e = g_es2[s] + ed;
        e = (e >= 0.f) ? e : 0.2f * e;
        float wt = __expf(e - m);
        z += wt;
        acc += wt * g_h2[(size_t)s * NCLS + fl];
    }
    float val = acc / z + b2[fl];
    float mx = val;
    #pragma unroll
    for (int o = 8; o; o >>= 1) mx = fmaxf(mx, __shfl_xor_sync(gmask, mx, o, 16));
    float ex = __expf(val - mx);
    float sev = ex;
    #pragma unroll
    for (int o = 8; o; o >>= 1) sev += __shfl_xor_sync(gmask, sev, o, 16);
    out[(size_t)node * NCLS + fl] = val - mx - logf(sev);
}

// ---------------- launch (single stream, graph-capture safe) ----------------
extern "C" void kernel_launch(void* const* d_in, const int* in_sizes, int n_in,
                              void* d_out, int out_size) {
    const float* x   = (const float*)d_in[0];
    const int*   ei  = (const int*)d_in[1];
    const float* W1  = (const float*)d_in[2];
    const float* as1 = (const float*)d_in[3];
    const float* ad1 = (const float*)d_in[4];
    const float* b1  = (const float*)d_in[5];
    const float* W2  = (const float*)d_in[6];
    const float* as2 = (const float*)d_in[7];
    const float* ad2 = (const float*)d_in[8];
    const float* b2  = (const float*)d_in[9];
    float* out = (float*)d_out;

    int N  = in_sizes[0] / IN_F;
    int E  = in_sizes[1] / 2;
    int nsb = (N + 1023) / 1024;
    int Eh = (E >> 1) + 1;   // 2 edges/thread (+1 thread for odd tail)

    k_gemm1  <<<(N + 63) / 64, 256>>>(x, W1, as1, ad1, N);
    k_hist   <<<(Eh + 255) / 256, 256>>>(ei, E);
    k_scan_a <<<nsb, 1024>>>(N);
    k_scan_c <<<nsb, 1024>>>(N);
    k_scatter<<<(Eh + 255) / 256, 256>>>(ei, E);
    k_agg1   <<<(N + 7) / 8, 256>>>(b1, N);
    k_gemm2  <<<(N + 255) / 256, 256>>>(W2, as2, ad2, N);
    k_agg2   <<<(N + 15) / 16, 256>>>(b2, out, N);
}